// round 14
// baseline (speedup 1.0000x reference)
#include <cuda_runtime.h>
#include <math.h>

// ---------------- scratch (no allocs allowed) ----------------
#define MAX_T (64 * 4096)
#define MAX_B 64
#define MAX_K 1024
__device__ float g_dot[MAX_T];          // per-node dot(logits, proj)
__device__ int   g_idx[MAX_B * MAX_K];  // selected node indices (ASCENDING order)

// ---------------- kernel 1: per-row dot product ----------------
// One warp per 4 rows; all 8 float4 loads issued before reduction (MLP=8).
__global__ void __launch_bounds__(512)
dot_kernel(const float* __restrict__ logits,
           const float* __restrict__ proj,
           float* __restrict__ dots,
           int rowBase, int rowEnd) {
    __shared__ float4 pS[64];
    int tid = threadIdx.x;
    if (tid < 64) pS[tid] = reinterpret_cast<const float4*>(proj)[tid];
    __syncthreads();

    int warp = tid >> 5, lane = tid & 31;
    int row0 = rowBase + (blockIdx.x * 16 + warp) * 4;
    if (row0 >= rowEnd) return;

    const float4* rp = reinterpret_cast<const float4*>(logits) + (size_t)row0 * 64;

    float4 a[4], c[4];
#pragma unroll
    for (int r = 0; r < 4; r++) {
        a[r] = rp[(size_t)r * 64 + lane];
        c[r] = rp[(size_t)r * 64 + lane + 32];
    }
    float4 pa = pS[lane];
    float4 pc = pS[lane + 32];

    float s[4];
#pragma unroll
    for (int r = 0; r < 4; r++) {
        s[r] = a[r].x * pa.x + a[r].y * pa.y + a[r].z * pa.z + a[r].w * pa.w
             + c[r].x * pc.x + c[r].y * pc.y + c[r].z * pc.z + c[r].w * pc.w;
#pragma unroll
        for (int o = 16; o; o >>= 1) s[r] += __shfl_xor_sync(0xFFFFFFFFu, s[r], o);
    }
    if (lane < 4) dots[row0 + lane] = s[lane];
}

// ---------------- kernel 2: radix select + ORDERED compaction ----------------
// One block (1024 threads) per graph. 4x 8-bit MSB-first radix passes with
// warp-aggregated histogram. Compaction emits indices in ASCENDING node order
// (deterministic, atomic-free) so the gather kernel walks memory
// quasi-sequentially (DRAM row-buffer friendly). Also zeroes the output row.
__global__ void __launch_bounds__(1024)
select_kernel(const float* __restrict__ dots,
              int* __restrict__ idxList,
              float* __restrict__ out,
              int N, int K, int D, int bBase) {
    __shared__ unsigned keys[4096];
    __shared__ unsigned hist[256];
    __shared__ unsigned warpTot[8];
    __shared__ unsigned s_chosen;
    __shared__ unsigned s_need;
    __shared__ int scanA[32];
    __shared__ int scanB[32];
    __shared__ int eqBase, selBase, chunkTotA, chunkTotB;

    int b = bBase + blockIdx.x, tid = threadIdx.x;
    int lane = tid & 31, warp = tid >> 5;
    const float* d = dots + (size_t)b * N;
    const unsigned FULL = 0xFFFFFFFFu;

    for (int i = tid; i < D; i += blockDim.x) out[(size_t)b * D + i] = 0.0f;

    for (int i = tid; i < N; i += blockDim.x) {
        unsigned u = __float_as_uint(d[i]);
        u ^= (u >> 31) ? 0xFFFFFFFFu : 0x80000000u;  // order-preserving
        keys[i] = u;
    }
    if (tid == 0) s_need = (unsigned)K;
    __syncthreads();

    unsigned prefix = 0, mask = 0;
#pragma unroll
    for (int pass = 0; pass < 4; pass++) {
        int shift = 24 - 8 * pass;
        unsigned need = s_need;
        if (tid < 256) hist[tid] = 0;
        __syncthreads();
        for (int i = tid; i < N; i += blockDim.x) {
            unsigned kk = keys[i];
            bool pred = ((kk & mask) == prefix);
            unsigned bin = (kk >> shift) & 0xFFu;
            unsigned act = __ballot_sync(FULL, pred);
            if (pred) {
                unsigned mm = __match_any_sync(act, bin);
                int leader = __ffs(mm) - 1;
                if (lane == leader) atomicAdd(&hist[bin], (unsigned)__popc(mm));
            }
        }
        __syncthreads();
        // two-level suffix scan over 256 bins (warps 0..7)
        if (warp < 8) {
            unsigned sum = hist[warp * 32 + lane];
#pragma unroll
            for (int o = 1; o < 32; o <<= 1) {
                unsigned t = __shfl_down_sync(FULL, sum, o);
                if (lane + o < 32) sum += t;
            }
            if (lane == 0) warpTot[warp] = sum;
            __syncwarp();
            hist[warp * 32 + lane] = sum;   // intra-warp inclusive suffix
        }
        __syncthreads();
        if (tid < 256) {
            unsigned add = 0;
            int myw = tid >> 5;
#pragma unroll
            for (int w = 0; w < 8; w++)
                if (w > myw) add += warpTot[w];
            unsigned st = hist[tid] + add;
            unsigned sn;
            if (tid == 255) sn = 0;
            else if ((tid & 31) == 31) sn = add;
            else sn = hist[tid + 1] + add;
            if (st >= need && sn < need) {
                s_chosen = (unsigned)tid;
                s_need = need - sn;
            }
        }
        __syncthreads();
        prefix |= s_chosen << shift;
        mask   |= 0xFFu << shift;
        __syncthreads();
    }

    unsigned thr = prefix;              // exact key of the k-th largest
    int budget = (int)s_need;           // # of EQ(thr) elements to take (by index order)
    if (tid == 0) { eqBase = 0; selBase = 0; }
    __syncthreads();

    int* lst = idxList + (size_t)b * K;
    unsigned lmLT = (1u << lane) - 1u;

    // ordered compaction: 4 chunks of 1024 consecutive indices
    for (int c = 0; c < N; c += 1024) {
        int i = c + tid;                     // N multiple of 1024 here
        unsigned kk = keys[i];
        bool isGT = (kk > thr), isEQ = (kk == thr);

        // scan 1: EQ rank (index order) for tie budget
        unsigned balEQ = __ballot_sync(FULL, isEQ);
        int eqLane = __popc(balEQ & lmLT);
        if (lane == 0) scanA[warp] = __popc(balEQ);
        __syncthreads();
        if (tid < 32) {
            int v = scanA[tid], s = v;
#pragma unroll
            for (int o = 1; o < 32; o <<= 1) {
                int t = __shfl_up_sync(FULL, s, o);
                if (tid >= o) s += t;
            }
            scanA[tid] = s - v;              // exclusive prefix
            if (tid == 31) chunkTotA = s;
        }
        __syncthreads();
        int eqRank = eqBase + scanA[warp] + eqLane;
        bool sel = isGT || (isEQ && eqRank < budget);

        // scan 2: output position among selected (index order)
        unsigned balS = __ballot_sync(FULL, sel);
        int selLane = __popc(balS & lmLT);
        if (lane == 0) scanB[warp] = __popc(balS);
        __syncthreads();
        if (tid < 32) {
            int v = scanB[tid], s = v;
#pragma unroll
            for (int o = 1; o < 32; o <<= 1) {
                int t = __shfl_up_sync(FULL, s, o);
                if (tid >= o) s += t;
            }
            scanB[tid] = s - v;              // exclusive prefix
            if (tid == 31) chunkTotB = s;
        }
        __syncthreads();
        if (sel) lst[selBase + scanB[warp] + selLane] = b * N + i;
        __syncthreads();
        if (tid == 0) { eqBase += chunkTotA; selBase += chunkTotB; }
        __syncthreads();
    }
}

// ---------------- kernel 3: gather + segment sum (direct-index, ascending) -------
// GSPLIT=32 -> 2048 blocks, 26 rows/slice (now ascending node order ->
// quasi-sequential DRAM). 256 threads = 4 row-groups x 64 lanes; group g owns
// rows g, g+4, ... (<=7). Index loads broadcast within group; all row float4
// loads issue as one predicated wave.
#define GSPLIT 32
__global__ void __launch_bounds__(256)
gather_sum_kernel(const float* __restrict__ logits,
                  const int* __restrict__ idxList,
                  float* __restrict__ out,
                  int K, int D, int bBase) {
    __shared__ float4 part[4][64];

    int b = bBase + blockIdx.x / GSPLIT;
    int s = blockIdx.x % GSPLIT;
    int tid = threadIdx.x;
    int grp = tid >> 6;        // 0..3
    int l64 = tid & 63;        // float4 column within row

    int per = (K + GSPLIT - 1) / GSPLIT;          // 26 for K=820
    int r0 = s * per;
    int cnt = min(K, r0 + per) - r0;              // >= 14 here

    const int* lst = idxList + (size_t)b * K + r0;

    int rows[7];
#pragma unroll
    for (int j = 0; j < 7; j++) {
        int r = grp + 4 * j;
        if (r < cnt) rows[j] = __ldg(&lst[r]);
    }

    const float4* lg4 = reinterpret_cast<const float4*>(logits);
    int nD4 = D >> 2;  // 64

    float4 v[7];
#pragma unroll
    for (int j = 0; j < 7; j++) {
        int r = grp + 4 * j;
        if (r < cnt) v[j] = lg4[(size_t)rows[j] * nD4 + l64];
    }

    float4 acc = make_float4(0.f, 0.f, 0.f, 0.f);
#pragma unroll
    for (int j = 0; j < 7; j++) {
        int r = grp + 4 * j;
        if (r < cnt) {
            acc.x += v[j].x; acc.y += v[j].y;
            acc.z += v[j].z; acc.w += v[j].w;
        }
    }
    part[grp][l64] = acc;
    __syncthreads();

    int col = tid >> 2, comp = tid & 3;
    const float* q0 = reinterpret_cast<const float*>(&part[0][col]);
    const float* q1 = reinterpret_cast<const float*>(&part[1][col]);
    const float* q2 = reinterpret_cast<const float*>(&part[2][col]);
    const float* q3 = reinterpret_cast<const float*>(&part[3][col]);
    float vsum = (q0[comp] + q1[comp]) + (q2[comp] + q3[comp]);
    atomicAdd(&out[(size_t)b * D + tid], vsum);
}

// ---------------- launcher: clean sequential pipeline ----------------
extern "C" void kernel_launch(void* const* d_in, const int* in_sizes, int n_in,
                              void* d_out, int out_size) {
    const float* logits = (const float*)d_in[0];
    const float* proj = (const float*)d_in[2];
    float* out = (float*)d_out;

    int D = in_sizes[2];                 // 256
    int T = in_sizes[1];                 // 262144
    int B = out_size / D;                // 64
    int N = T / B;                       // 4096
    int K = (int)ceil(0.2 * (double)N);  // 820

    float* dots;
    int* idxList;
    cudaGetSymbolAddress((void**)&dots, g_dot);
    cudaGetSymbolAddress((void**)&idxList, g_idx);

    // 1) per-node dot products (monotone proxy for sigmoid score)
    dot_kernel<<<(T + 63) / 64, 512>>>(logits, proj, dots, 0, T);

    // 2) per-graph exact top-K selection, ascending-index output (also zeroes out)
    select_kernel<<<B, 1024>>>(dots, idxList, out, N, K, D, 0);

    // 3) gather + segment sum (quasi-sequential access)
    gather_sum_kernel<<<B * GSPLIT, 256>>>(logits, idxList, out, K, D, 0);
}